// round 12
// baseline (speedup 1.0000x reference)
#include <cuda_runtime.h>
#include <cuda_bf16.h>
#include <math.h>
#include <stdint.h>

#define N_IMG 128
#define N_REG 36
#define N_CAP 128
#define N_WORD 32
#define DIM 1024
#define LAMBDA_S 20.0f
#define EPSV 1e-8f

#define M_TOT (N_CAP * N_WORD)   // 4096
#define N_TOT (N_IMG * N_REG)    // 4608

// ---------------- scratch (static device globals; allocation-free) ---------
__device__ float g_sim[(size_t)M_TOT * N_TOT];          // sim[m][n]
__device__ __nv_bfloat16 g_Ahi[(size_t)M_TOT * DIM];    // captions hi
__device__ __nv_bfloat16 g_Alo[(size_t)M_TOT * DIM];    // captions lo
__device__ __nv_bfloat16 g_Bhi[(size_t)N_TOT * DIM];    // images hi
__device__ __nv_bfloat16 g_Blo[(size_t)N_TOT * DIM];    // images lo
__device__ float g_G[N_IMG * N_REG * N_REG];            // image Grams
__device__ float g_H[N_CAP * N_WORD * N_WORD];          // caption Grams
__device__ float g_imn[N_IMG * N_REG];                  // image region norms
__device__ float g_cpn[N_CAP * N_WORD];                 // caption word norms

__device__ __forceinline__ uint32_t smem_u32(const void* p) {
    uint32_t a;
    asm("{ .reg .u64 t; cvta.to.shared.u64 t, %1; cvt.u32.u64 %0, t; }"
        : "=r"(a) : "l"(p));
    return a;
}

#define SWZ(x) ((x) ^ (((x) >> 3) & 0x70))

// ---------------------------------------------------------------------------
// Kernel 0: merged prologue.
//   blocks 0..2047    : fp32 -> bf16 hi/lo split (grid-stride)
//   blocks 2048..2303 : Gram matrices + norms (one image/caption each)
// ---------------------------------------------------------------------------
__global__ void __launch_bounds__(256) prep_kernel(const float* __restrict__ images,
                                                   const float* __restrict__ captions) {
    __shared__ float4 sh[N_REG * 16];   // used only by gram branch
    int t = threadIdx.x;

    if (blockIdx.x < 2048) {
        // ---------------- split ----------------
        const int capF4 = M_TOT * DIM / 4;
        const int imgF4 = N_TOT * DIM / 4;
        const int total = capF4 + imgF4;
        for (int idx = blockIdx.x * 256 + t; idx < total; idx += 2048 * 256) {
            const float4* src;
            __nv_bfloat16 *hi, *lo;
            int o;
            if (idx < capF4) { src = (const float4*)captions; o = idx; hi = g_Ahi; lo = g_Alo; }
            else             { src = (const float4*)images;  o = idx - capF4; hi = g_Bhi; lo = g_Blo; }
            float4 v = src[o];
            float vv[4] = {v.x, v.y, v.z, v.w};
            __nv_bfloat16 h[4], l[4];
#pragma unroll
            for (int j = 0; j < 4; j++) {
                h[j] = __float2bfloat16(vv[j]);
                l[j] = __float2bfloat16(vv[j] - __bfloat162float(h[j]));
            }
            *(uint2*)(hi + 4 * (size_t)o) = *(uint2*)h;
            *(uint2*)(lo + 4 * (size_t)o) = *(uint2*)l;
        }
        return;
    }

    // ---------------- gram ----------------
    int b = blockIdx.x - 2048;          // 0..255
    bool isImg = b < N_IMG;
    int S = isImg ? N_REG : N_WORD;
    const float* base = isImg ? images + (size_t)b * N_REG * DIM
                              : captions + (size_t)(b - N_IMG) * N_WORD * DIM;
    float* gout = isImg ? g_G + b * N_REG * N_REG : g_H + (b - N_IMG) * N_WORD * N_WORD;
    float* nout = isImg ? g_imn + b * N_REG : g_cpn + (b - N_IMG) * N_WORD;

    int ti = t / 12, tj = t % 12;
    int r1b = ti * 3, r2b = tj * 3;
    float acc[3][3] = {{0.f,0.f,0.f},{0.f,0.f,0.f},{0.f,0.f,0.f}};

    for (int dc = 0; dc < DIM; dc += 64) {
        __syncthreads();
        for (int e = t; e < S * 16; e += 256) {
            int r = e >> 4, c = e & 15;
            sh[e] = *(const float4*)(base + (size_t)r * DIM + dc + c * 4);
        }
        __syncthreads();
        if (t < 144 && r1b < S && r2b < S) {
            int i0 = min(r1b + 0, S - 1) * 16, i1 = min(r1b + 1, S - 1) * 16,
                i2 = min(r1b + 2, S - 1) * 16;
            int j0 = min(r2b + 0, S - 1) * 16, j1 = min(r2b + 1, S - 1) * 16,
                j2 = min(r2b + 2, S - 1) * 16;
#pragma unroll 4
            for (int k = 0; k < 16; k++) {
                float4 a0 = sh[i0 + k], a1 = sh[i1 + k], a2 = sh[i2 + k];
                float4 c0 = sh[j0 + k], c1 = sh[j1 + k], c2 = sh[j2 + k];
#define DOT4(A, C) ((A).x * (C).x + (A).y * (C).y + (A).z * (C).z + (A).w * (C).w)
                acc[0][0] += DOT4(a0, c0); acc[0][1] += DOT4(a0, c1); acc[0][2] += DOT4(a0, c2);
                acc[1][0] += DOT4(a1, c0); acc[1][1] += DOT4(a1, c1); acc[1][2] += DOT4(a1, c2);
                acc[2][0] += DOT4(a2, c0); acc[2][1] += DOT4(a2, c1); acc[2][2] += DOT4(a2, c2);
#undef DOT4
            }
        }
    }
    if (t < 144) {
#pragma unroll
        for (int ii = 0; ii < 3; ii++)
#pragma unroll
            for (int jj = 0; jj < 3; jj++) {
                int r1 = r1b + ii, r2 = r2b + jj;
                if (r1 < S && r2 < S) {
                    gout[r1 * S + r2] = acc[ii][jj];
                    if (r1 == r2) nout[r1] = sqrtf(acc[ii][jj]);
                }
            }
    }
}

// ---------------------------------------------------------------------------
// Kernel 2: warp-MMA bf16-split GEMM with cp.async double buffering.
// 128x128 CTA tile, 8 warps x (64x32), 2 CTAs/SM.  (R7 config — proven best)
// ---------------------------------------------------------------------------
#define KC 64
#define TILE_B (128 * KC * 2)        // 16384 bytes per operand tile
#define STAGE_B (2 * TILE_B)         // 32768
#define GEMM_SMEM (2 * STAGE_B)      // 65536
#define NCHUNK 48                    // 3 terms x 16 chunks

__device__ __forceinline__ void ldm_x4(uint32_t& r0, uint32_t& r1, uint32_t& r2,
                                       uint32_t& r3, uint32_t addr) {
    asm volatile("ldmatrix.sync.aligned.m8n8.x4.shared.b16 {%0,%1,%2,%3}, [%4];"
                 : "=r"(r0), "=r"(r1), "=r"(r2), "=r"(r3) : "r"(addr));
}

__device__ __forceinline__ void mma_16816(float* c, const uint32_t* a, uint32_t b0,
                                          uint32_t b1) {
    asm volatile(
        "mma.sync.aligned.m16n8k16.row.col.f32.bf16.bf16.f32 "
        "{%0,%1,%2,%3}, {%4,%5,%6,%7}, {%8,%9}, {%0,%1,%2,%3};"
        : "+f"(c[0]), "+f"(c[1]), "+f"(c[2]), "+f"(c[3])
        : "r"(a[0]), "r"(a[1]), "r"(a[2]), "r"(a[3]), "r"(b0), "r"(b1));
}

__device__ __forceinline__ void cp16(uint32_t dst, const void* src) {
    asm volatile("cp.async.cg.shared.global [%0], [%1], 16;" :: "r"(dst), "l"(src));
}

__global__ void __launch_bounds__(256, 2) gemm_mma() {
    extern __shared__ char smem[];
    uint32_t sb = smem_u32(smem);
    int tid = threadIdx.x, wid = tid >> 5, lane = tid & 31;
    int bn = blockIdx.x * 128;
    int bm = blockIdx.y * 128;
    int wm = (wid >> 2) * 64;
    int wn = (wid & 3) * 32;

    const __nv_bfloat16* Aterm[3] = {g_Ahi + (size_t)bm * DIM, g_Ahi + (size_t)bm * DIM,
                                     g_Alo + (size_t)bm * DIM};
    const __nv_bfloat16* Bterm[3] = {g_Bhi + (size_t)bn * DIM, g_Blo + (size_t)bn * DIM,
                                     g_Bhi + (size_t)bn * DIM};

    float acc[4][4][4];
#pragma unroll
    for (int i = 0; i < 4; i++)
#pragma unroll
        for (int j = 0; j < 4; j++)
#pragma unroll
            for (int k = 0; k < 4; k++) acc[i][j][k] = 0.0f;

    int lr = lane & 7, sel = lane >> 3;
    int a_row = lr + ((sel & 1) << 3);
    int a_byte = (sel & 2) << 3;
    int b_row = lr + ((sel & 2) << 2);
    int b_byte = (sel & 1) << 4;

    int g_row = tid >> 3;
    int g_c16 = tid & 7;
    int ldrows[4], sts_off[4];
#pragma unroll
    for (int i = 0; i < 4; i++) {
        ldrows[i] = g_row + i * 32;
        sts_off[i] = SWZ(ldrows[i] * 128 + g_c16 * 16);
    }

#define ISSUE_CHUNK(ch, s)                                                      \
    {                                                                           \
        int term = (ch) >> 4, kc = (ch) & 15;                                   \
        const __nv_bfloat16* As = Aterm[term] + kc * KC;                        \
        const __nv_bfloat16* Bs = Bterm[term] + kc * KC;                        \
        uint32_t st = sb + (s) * STAGE_B;                                       \
        _Pragma("unroll") for (int i = 0; i < 4; i++) {                         \
            cp16(st + sts_off[i], As + (size_t)ldrows[i] * DIM + g_c16 * 8);    \
            cp16(st + TILE_B + sts_off[i],                                      \
                 Bs + (size_t)ldrows[i] * DIM + g_c16 * 8);                     \
        }                                                                       \
        asm volatile("cp.async.commit_group;" ::: "memory");                    \
    }

    ISSUE_CHUNK(0, 0);

    for (int ch = 0; ch < NCHUNK; ch++) {
        int s = ch & 1;
        if (ch + 1 < NCHUNK) {
            ISSUE_CHUNK(ch + 1, s ^ 1);
            asm volatile("cp.async.wait_group 1;" ::: "memory");
        } else {
            asm volatile("cp.async.wait_group 0;" ::: "memory");
        }
        __syncthreads();

        uint32_t sa = sb + s * STAGE_B;
        uint32_t sB = sa + TILE_B;
#pragma unroll
        for (int ks = 0; ks < 4; ks++) {
            uint32_t a[4][4], bb[2][4];
#pragma unroll
            for (int mf = 0; mf < 4; mf++) {
                uint32_t addr = sa + SWZ((wm + mf * 16 + a_row) * 128 + ks * 32 + a_byte);
                ldm_x4(a[mf][0], a[mf][1], a[mf][2], a[mf][3], addr);
            }
#pragma unroll
            for (int nh = 0; nh < 2; nh++) {
                uint32_t addr = sB + SWZ((wn + nh * 16 + b_row) * 128 + ks * 32 + b_byte);
                ldm_x4(bb[nh][0], bb[nh][1], bb[nh][2], bb[nh][3], addr);
            }
#pragma unroll
            for (int mf = 0; mf < 4; mf++)
#pragma unroll
                for (int nf = 0; nf < 4; nf++)
                    mma_16816(acc[mf][nf], a[mf], bb[nf >> 1][(nf & 1) * 2],
                              bb[nf >> 1][(nf & 1) * 2 + 1]);
        }
        __syncthreads();
    }

    int g = lane >> 2, t4 = lane & 3;
#pragma unroll
    for (int mf = 0; mf < 4; mf++) {
#pragma unroll
        for (int nf = 0; nf < 4; nf++) {
            int row0 = bm + wm + mf * 16 + g;
            int col = bn + wn + nf * 8 + 2 * t4;
            float* p0 = g_sim + (size_t)row0 * N_TOT + col;
            float* p1 = p0 + 8 * N_TOT;
            *(float2*)p0 = make_float2(acc[mf][nf][0], acc[mf][nf][1]);
            *(float2*)p1 = make_float2(acc[mf][nf][2], acc[mf][nf][3]);
        }
    }
}

// ---------------------------------------------------------------------------
// Kernel 3: fused focal attention, thread-per-query + f32x2 quadratic forms,
// LDS.128 Gram rows, dual q-accumulator chains (even/odd rows).
// Block = 288 threads = 4 pairs (same image, 4 captions), all parallel:
//   tid 0..127  : t2i, p = tid>>5, word w = tid&31
//   tid 128..271: i2t, k = tid-128, p = k/36, region r = k%36
// ---------------------------------------------------------------------------
#define PPB 4

typedef unsigned long long ull;

__device__ __forceinline__ ull pk2(float x, float y) {
    ull r;
    asm("mov.b64 %0, {%1, %2};" : "=l"(r) : "f"(x), "f"(y));
    return r;
}
__device__ __forceinline__ void upk2(float& x, float& y, ull v) {
    asm("mov.b64 {%0, %1}, %2;" : "=f"(x), "=f"(y) : "l"(v));
}
__device__ __forceinline__ void fma2(ull& acc, ull a, ull b) {
    asm("fma.rn.f32x2 %0, %1, %2, %0;" : "+l"(acc) : "l"(a), "l"(b));
}
__device__ __forceinline__ ull add2(ull a, ull b) {
    ull r;
    asm("add.rn.f32x2 %0, %1, %2;" : "=l"(r) : "l"(a), "l"(b));
    return r;
}

__global__ void __launch_bounds__(288, 3) attn_kernel(float* __restrict__ out) {
    __shared__ float raw[PPB][N_REG][N_WORD + 1];             // 19008 B
    __shared__ __align__(16) float G[N_REG][N_REG];           // 5184 B
    __shared__ __align__(16) float Hs[PPB][N_WORD][N_WORD];   // 16384 B
    __shared__ float nrmi[PPB][N_REG];
    __shared__ float nrmw[PPB][N_WORD];
    __shared__ float imn[N_REG];
    __shared__ float cpn[PPB][N_WORD];
    __shared__ float red[PPB][68];

    int i = blockIdx.y, c0 = blockIdx.x * PPB, t = threadIdx.x;

    // ---- loads ----
    for (int e = t; e < PPB * N_REG * N_WORD; e += 288) {
        int p = e / (N_REG * N_WORD), k = e % (N_REG * N_WORD);
        int w = k / N_REG, r = k % N_REG;
        raw[p][r][w] = g_sim[(size_t)((c0 + p) * N_WORD + w) * N_TOT + i * N_REG + r];
    }
    for (int e = t; e < N_REG * N_REG; e += 288)
        G[e / N_REG][e % N_REG] = g_G[i * N_REG * N_REG + e];
    for (int e = t; e < PPB * N_WORD * N_WORD; e += 288) {
        int p = e >> 10, k = e & 1023;
        Hs[p][k >> 5][k & 31] = g_H[(c0 + p) * N_WORD * N_WORD + k];
    }
    if (t < N_REG) imn[t] = g_imn[i * N_REG + t];
    if (t >= 128 && t < 128 + PPB * N_WORD) {
        int k = t - 128;
        cpn[k >> 5][k & 31] = g_cpn[(c0 + (k >> 5)) * N_WORD + (k & 31)];
    }
    __syncthreads();

    // ---- norms (task-per-thread matches query mapping) ----
    if (t < 128) {
        int p = t >> 5, w = t & 31;   // i2t needs nrmw
        float s = 0.0f;
#pragma unroll
        for (int r = 0; r < N_REG; r++) {
            float x = raw[p][r][w];
            x = (x >= 0.0f) ? x : 0.1f * x;
            s += x * x;
        }
        nrmw[p][w] = 1.0f / (sqrtf(s) + EPSV);
    } else if (t < 272) {
        int k = t - 128, p = k / N_REG, r = k % N_REG;  // t2i needs nrmi
        float s = 0.0f;
#pragma unroll
        for (int w = 0; w < N_WORD; w++) {
            float x = raw[p][r][w];
            x = (x >= 0.0f) ? x : 0.1f * x;
            s += x * x;
        }
        nrmi[p][r] = 1.0f / (sqrtf(s) + EPSV);
    }
    __syncthreads();

    if (t < 128) {
        // ================= t2i: one word per thread, S = 36 regions ==========
        int p = t >> 5, w = t & 31;
        ull a2[18];
        float mx = -1e30f;
#pragma unroll
        for (int rp = 0; rp < 18; rp++) {
            float x0 = raw[p][2 * rp][w], x1 = raw[p][2 * rp + 1][w];
            x0 = (x0 >= 0.0f) ? x0 : 0.1f * x0;
            x1 = (x1 >= 0.0f) ? x1 : 0.1f * x1;
            x0 *= nrmi[p][2 * rp];
            x1 *= nrmi[p][2 * rp + 1];
            mx = fmaxf(mx, fmaxf(x0, x1));
            a2[rp] = pk2(x0, x1);
        }
        float s = 0.0f;
#pragma unroll
        for (int rp = 0; rp < 18; rp++) {
            float x0, x1; upk2(x0, x1, a2[rp]);
            x0 = __expf(LAMBDA_S * (x0 - mx));
            x1 = __expf(LAMBDA_S * (x1 - mx));
            s += x0 + x1;
            a2[rp] = pk2(x0, x1);
        }
        float inv = 1.0f / s;
        float sum1 = 0.0f;
#pragma unroll
        for (int rp = 0; rp < 18; rp++) {
            float x0, x1; upk2(x0, x1, a2[rp]);
            x0 *= inv; x1 *= inv;
            sum1 += x0 + x1;
            a2[rp] = pk2(x0, x1);
        }
        float st = 0.0f;
#pragma unroll
        for (int rp = 0; rp < 18; rp++) {
            float x0, x1; upk2(x0, x1, a2[rp]);
            x0 = (x0 * (float)N_REG - sum1 > 0.0f) ? x0 : 0.0f;
            x1 = (x1 * (float)N_REG - sum1 > 0.0f) ? x1 : 0.0f;
            st += x0 + x1;
            a2[rp] = pk2(x0, x1);
        }
        float invst = 1.0f / st;
        float num = 0.0f;
#pragma unroll
        for (int rp = 0; rp < 18; rp++) {
            float x0, x1; upk2(x0, x1, a2[rp]);
            x0 *= invst; x1 *= invst;
            num += x0 * raw[p][2 * rp][w] + x1 * raw[p][2 * rp + 1][w];
            a2[rp] = pk2(x0, x1);
        }
        // quadratic form q = a^T G a  (dual q chains over even/odd rows)
        float q0 = 0.0f, q1 = 0.0f;
#pragma unroll
        for (int rp = 0; rp < 18; rp++) {
            float ae, ao; upk2(ae, ao, a2[rp]);
            {
                const double2* Gr = (const double2*)&G[2 * rp][0];
                ull acc0 = 0, acc1 = 0;
#pragma unroll
                for (int j = 0; j < 9; j++) {
                    double2 g2 = Gr[j];
                    fma2(acc0, __double_as_longlong(g2.x), a2[2 * j]);
                    fma2(acc1, __double_as_longlong(g2.y), a2[2 * j + 1]);
                }
                float dx, dy; upk2(dx, dy, add2(acc0, acc1));
                q0 = fmaf(ae, dx + dy, q0);
            }
            {
                const double2* Gr = (const double2*)&G[2 * rp + 1][0];
                ull acc0 = 0, acc1 = 0;
#pragma unroll
                for (int j = 0; j < 9; j++) {
                    double2 g2 = Gr[j];
                    fma2(acc0, __double_as_longlong(g2.x), a2[2 * j]);
                    fma2(acc1, __double_as_longlong(g2.y), a2[2 * j + 1]);
                }
                float dx, dy; upk2(dx, dy, add2(acc0, acc1));
                q1 = fmaf(ao, dx + dy, q1);
            }
        }
        float q = q0 + q1;
        float nb = fmaxf(sqrtf(fmaxf(q, 0.0f)), EPSV);
        red[p][w] = num / (fmaxf(cpn[p][w], EPSV) * nb);
    } else if (t < 272) {
        // ================= i2t: one region per thread, S = 32 words ==========
        int k = t - 128, p = k / N_REG, r = k % N_REG;
        ull a2[16];
        float mx = -1e30f;
#pragma unroll
        for (int wp = 0; wp < 16; wp++) {
            float x0 = raw[p][r][2 * wp], x1 = raw[p][r][2 * wp + 1];
            x0 = (x0 >= 0.0f) ? x0 : 0.1f * x0;
            x1 = (x1 >= 0.0f) ? x1 : 0.1f * x1;
            x0 *= nrmw[p][2 * wp];
            x1 *= nrmw[p][2 * wp + 1];
            mx = fmaxf(mx, fmaxf(x0, x1));
            a2[wp] = pk2(x0, x1);
        }
        float s = 0.0f;
#pragma unroll
        for (int wp = 0; wp < 16; wp++) {
            float x0, x1; upk2(x0, x1, a2[wp]);
            x0 = __expf(LAMBDA_S * (x0 - mx));
            x1 = __expf(LAMBDA_S * (x1 - mx));
            s += x0 + x1;
            a2[wp] = pk2(x0, x1);
        }
        float inv = 1.0f / s;
        float sum1 = 0.0f;
#pragma unroll
        for (int wp = 0; wp < 16; wp++) {
            float x0, x1; upk2(x0, x1, a2[wp]);
            x0 *= inv; x1 *= inv;
            sum1 += x0 + x1;
            a2[wp] = pk2(x0, x1);
        }
        float st = 0.0f;
#pragma unroll
        for (int wp = 0; wp < 16; wp++) {
            float x0, x1; upk2(x0, x1, a2[wp]);
            x0 = (x0 * (float)N_WORD - sum1 > 0.0f) ? x0 : 0.0f;
            x1 = (x1 * (float)N_WORD - sum1 > 0.0f) ? x1 : 0.0f;
            st += x0 + x1;
            a2[wp] = pk2(x0, x1);
        }
        float invst = 1.0f / st;
        float num = 0.0f;
#pragma unroll
        for (int wp = 0; wp < 16; wp++) {
            float x0, x1; upk2(x0, x1, a2[wp]);
            x0 *= invst; x1 *= invst;
            num += x0 * raw[p][r][2 * wp] + x1 * raw[p][r][2 * wp + 1];
            a2[wp] = pk2(x0, x1);
        }
        float q0 = 0.0f, q1 = 0.0f;
#pragma unroll
        for (int wp = 0; wp < 16; wp++) {
            float ae, ao; upk2(ae, ao, a2[wp]);
            {
                const double2* Hr = (const double2*)&Hs[p][2 * wp][0];
                ull acc0 = 0, acc1 = 0;
#pragma unroll
                for (int j = 0; j < 8; j++) {
                    double2 g2 = Hr[j];
                    fma2(acc0, __double_as_longlong(g2.x), a2[2 * j]);
                    fma2(acc1, __double_as_longlong(g2.y), a2[2 * j + 1]);
                }
                float dx, dy; upk2(dx, dy, add2(acc0, acc1));
                q0 = fmaf(ae, dx + dy, q0);
            }
            {
                const double2* Hr = (const double2*)&Hs[p][2 * wp + 1][0];
                ull acc0 = 0, acc1 = 0;
#pragma unroll
                for (int j = 0; j < 8; j++) {
                    double2 g2 = Hr[j];
                    fma2(acc0, __double_as_longlong(g2.x), a2[2 * j]);
                    fma2(acc1, __double_as_longlong(g2.y), a2[2 * j + 1]);
                }
                float dx, dy; upk2(dx, dy, add2(acc0, acc1));
                q1 = fmaf(ao, dx + dy, q1);
            }
        }
        float q = q0 + q1;
        float nb = fmaxf(sqrtf(fmaxf(q, 0.0f)), EPSV);
        red[p][32 + r] = num / (fmaxf(imn[r], EPSV) * nb);
    }
    __syncthreads();

    if (t < PPB) {
        float s1 = 0.0f;
#pragma unroll
        for (int w = 0; w < N_WORD; w++) s1 += red[t][w];
        float s2 = 0.0f;
#pragma unroll
        for (int r = 0; r < N_REG; r++) s2 += red[t][32 + r];
        out[i * N_CAP + (c0 + t)] = s1 / (float)N_WORD + s2 / (float)N_REG;
    }
}

// ---------------------------------------------------------------------------
extern "C" void kernel_launch(void* const* d_in, const int* in_sizes, int n_in,
                              void* d_out, int out_size) {
    const float* images = (const float*)d_in[0];
    const float* captions = (const float*)d_in[1];
    float* out = (float*)d_out;

    cudaFuncSetAttribute(gemm_mma, cudaFuncAttributeMaxDynamicSharedMemorySize,
                         GEMM_SMEM);

    prep_kernel<<<2304, 256>>>(images, captions);
    gemm_mma<<<dim3(N_TOT / 128, M_TOT / 128), 256, GEMM_SMEM>>>();
    attn_kernel<<<dim3(N_CAP / PPB, N_IMG), 288>>>(out);
}

// round 13
// speedup vs baseline: 1.3645x; 1.3645x over previous
#include <cuda_runtime.h>
#include <cuda_bf16.h>
#include <math.h>
#include <stdint.h>

#define N_IMG 128
#define N_REG 36
#define N_CAP 128
#define N_WORD 32
#define DIM 1024
#define LAMBDA_S 20.0f
#define EPSV 1e-8f

#define M_TOT (N_CAP * N_WORD)   // 4096
#define N_TOT (N_IMG * N_REG)    // 4608

// ---------------- scratch (static device globals; allocation-free) ---------
__device__ float g_sim[(size_t)M_TOT * N_TOT];          // sim[m][n]
__device__ __nv_bfloat16 g_Ahi[(size_t)M_TOT * DIM];    // captions hi
__device__ __nv_bfloat16 g_Alo[(size_t)M_TOT * DIM];    // captions lo
__device__ __nv_bfloat16 g_Bhi[(size_t)N_TOT * DIM];    // images hi
__device__ __nv_bfloat16 g_Blo[(size_t)N_TOT * DIM];    // images lo
__device__ float g_G[N_IMG * N_REG * N_REG];            // image Grams
__device__ float g_H[N_CAP * N_WORD * N_WORD];          // caption Grams
__device__ float g_imn[N_IMG * N_REG];                  // image region norms
__device__ float g_cpn[N_CAP * N_WORD];                 // caption word norms

__device__ __forceinline__ uint32_t smem_u32(const void* p) {
    uint32_t a;
    asm("{ .reg .u64 t; cvta.to.shared.u64 t, %1; cvt.u32.u64 %0, t; }"
        : "=r"(a) : "l"(p));
    return a;
}

#define SWZ(x) ((x) ^ (((x) >> 3) & 0x70))

// ---------------------------------------------------------------------------
// Kernel 0: fp32 -> bf16 hi/lo split of captions and images
// ---------------------------------------------------------------------------
__global__ void __launch_bounds__(256) split_kernel(const float* __restrict__ images,
                                                    const float* __restrict__ captions) {
    const int capF4 = M_TOT * DIM / 4;
    const int imgF4 = N_TOT * DIM / 4;
    const int total = capF4 + imgF4;
    for (int idx = blockIdx.x * blockDim.x + threadIdx.x; idx < total;
         idx += gridDim.x * blockDim.x) {
        const float4* src;
        __nv_bfloat16 *hi, *lo;
        int o;
        if (idx < capF4) { src = (const float4*)captions; o = idx; hi = g_Ahi; lo = g_Alo; }
        else             { src = (const float4*)images;  o = idx - capF4; hi = g_Bhi; lo = g_Blo; }
        float4 v = src[o];
        float vv[4] = {v.x, v.y, v.z, v.w};
        __nv_bfloat16 h[4], l[4];
#pragma unroll
        for (int j = 0; j < 4; j++) {
            h[j] = __float2bfloat16(vv[j]);
            l[j] = __float2bfloat16(vv[j] - __bfloat162float(h[j]));
        }
        *(uint2*)(hi + 4 * (size_t)o) = *(uint2*)h;
        *(uint2*)(lo + 4 * (size_t)o) = *(uint2*)l;
    }
}

// ---------------------------------------------------------------------------
// Kernel 1: Gram matrices + norms. PADDED shared rows (17 float4 = 68 floats,
// stride % 32 banks = 4) — kills the 12-way bank conflict of the 64-float rows.
// ---------------------------------------------------------------------------
#define GROW 17
__global__ void __launch_bounds__(256) gram_kernel(const float* __restrict__ images,
                                                   const float* __restrict__ captions) {
    __shared__ float4 sh[N_REG * GROW];
    int b = blockIdx.x, t = threadIdx.x;
    bool isImg = b < N_IMG;
    int S = isImg ? N_REG : N_WORD;
    const float* base = isImg ? images + (size_t)b * N_REG * DIM
                              : captions + (size_t)(b - N_IMG) * N_WORD * DIM;
    float* gout = isImg ? g_G + b * N_REG * N_REG : g_H + (b - N_IMG) * N_WORD * N_WORD;
    float* nout = isImg ? g_imn + b * N_REG : g_cpn + (b - N_IMG) * N_WORD;

    int ti = t / 12, tj = t % 12;
    int r1b = ti * 3, r2b = tj * 3;
    float acc[3][3] = {{0.f,0.f,0.f},{0.f,0.f,0.f},{0.f,0.f,0.f}};

    for (int dc = 0; dc < DIM; dc += 64) {
        __syncthreads();
        for (int e = t; e < S * 16; e += 256) {
            int r = e >> 4, c = e & 15;
            sh[r * GROW + c] = *(const float4*)(base + (size_t)r * DIM + dc + c * 4);
        }
        __syncthreads();
        if (t < 144 && r1b < S && r2b < S) {
            int i0 = min(r1b + 0, S - 1) * GROW, i1 = min(r1b + 1, S - 1) * GROW,
                i2 = min(r1b + 2, S - 1) * GROW;
            int j0 = min(r2b + 0, S - 1) * GROW, j1 = min(r2b + 1, S - 1) * GROW,
                j2 = min(r2b + 2, S - 1) * GROW;
#pragma unroll 4
            for (int k = 0; k < 16; k++) {
                float4 a0 = sh[i0 + k], a1 = sh[i1 + k], a2 = sh[i2 + k];
                float4 c0 = sh[j0 + k], c1 = sh[j1 + k], c2 = sh[j2 + k];
#define DOT4(A, C) ((A).x * (C).x + (A).y * (C).y + (A).z * (C).z + (A).w * (C).w)
                acc[0][0] += DOT4(a0, c0); acc[0][1] += DOT4(a0, c1); acc[0][2] += DOT4(a0, c2);
                acc[1][0] += DOT4(a1, c0); acc[1][1] += DOT4(a1, c1); acc[1][2] += DOT4(a1, c2);
                acc[2][0] += DOT4(a2, c0); acc[2][1] += DOT4(a2, c1); acc[2][2] += DOT4(a2, c2);
#undef DOT4
            }
        }
    }
    if (t < 144) {
#pragma unroll
        for (int ii = 0; ii < 3; ii++)
#pragma unroll
            for (int jj = 0; jj < 3; jj++) {
                int r1 = r1b + ii, r2 = r2b + jj;
                if (r1 < S && r2 < S) {
                    gout[r1 * S + r2] = acc[ii][jj];
                    if (r1 == r2) nout[r1] = sqrtf(acc[ii][jj]);
                }
            }
    }
}

// ---------------------------------------------------------------------------
// Kernel 2: warp-MMA bf16-split GEMM with cp.async double buffering.
// 128x128 CTA tile, 8 warps x (64x32), 2 CTAs/SM.  (R7 config — proven best)
// ---------------------------------------------------------------------------
#define KC 64
#define TILE_B (128 * KC * 2)        // 16384 bytes per operand tile
#define STAGE_B (2 * TILE_B)         // 32768
#define GEMM_SMEM (2 * STAGE_B)      // 65536
#define NCHUNK 48                    // 3 terms x 16 chunks

__device__ __forceinline__ void ldm_x4(uint32_t& r0, uint32_t& r1, uint32_t& r2,
                                       uint32_t& r3, uint32_t addr) {
    asm volatile("ldmatrix.sync.aligned.m8n8.x4.shared.b16 {%0,%1,%2,%3}, [%4];"
                 : "=r"(r0), "=r"(r1), "=r"(r2), "=r"(r3) : "r"(addr));
}

__device__ __forceinline__ void mma_16816(float* c, const uint32_t* a, uint32_t b0,
                                          uint32_t b1) {
    asm volatile(
        "mma.sync.aligned.m16n8k16.row.col.f32.bf16.bf16.f32 "
        "{%0,%1,%2,%3}, {%4,%5,%6,%7}, {%8,%9}, {%0,%1,%2,%3};"
        : "+f"(c[0]), "+f"(c[1]), "+f"(c[2]), "+f"(c[3])
        : "r"(a[0]), "r"(a[1]), "r"(a[2]), "r"(a[3]), "r"(b0), "r"(b1));
}

__device__ __forceinline__ void cp16(uint32_t dst, const void* src) {
    asm volatile("cp.async.cg.shared.global [%0], [%1], 16;" :: "r"(dst), "l"(src));
}

__global__ void __launch_bounds__(256, 2) gemm_mma() {
    extern __shared__ char smem[];
    uint32_t sb = smem_u32(smem);
    int tid = threadIdx.x, wid = tid >> 5, lane = tid & 31;
    int bn = blockIdx.x * 128;
    int bm = blockIdx.y * 128;
    int wm = (wid >> 2) * 64;
    int wn = (wid & 3) * 32;

    const __nv_bfloat16* Aterm[3] = {g_Ahi + (size_t)bm * DIM, g_Ahi + (size_t)bm * DIM,
                                     g_Alo + (size_t)bm * DIM};
    const __nv_bfloat16* Bterm[3] = {g_Bhi + (size_t)bn * DIM, g_Blo + (size_t)bn * DIM,
                                     g_Bhi + (size_t)bn * DIM};

    float acc[4][4][4];
#pragma unroll
    for (int i = 0; i < 4; i++)
#pragma unroll
        for (int j = 0; j < 4; j++)
#pragma unroll
            for (int k = 0; k < 4; k++) acc[i][j][k] = 0.0f;

    int lr = lane & 7, sel = lane >> 3;
    int a_row = lr + ((sel & 1) << 3);
    int a_byte = (sel & 2) << 3;
    int b_row = lr + ((sel & 2) << 2);
    int b_byte = (sel & 1) << 4;

    int g_row = tid >> 3;
    int g_c16 = tid & 7;
    int ldrows[4], sts_off[4];
#pragma unroll
    for (int i = 0; i < 4; i++) {
        ldrows[i] = g_row + i * 32;
        sts_off[i] = SWZ(ldrows[i] * 128 + g_c16 * 16);
    }

#define ISSUE_CHUNK(ch, s)                                                      \
    {                                                                           \
        int term = (ch) >> 4, kc = (ch) & 15;                                   \
        const __nv_bfloat16* As = Aterm[term] + kc * KC;                        \
        const __nv_bfloat16* Bs = Bterm[term] + kc * KC;                        \
        uint32_t st = sb + (s) * STAGE_B;                                       \
        _Pragma("unroll") for (int i = 0; i < 4; i++) {                         \
            cp16(st + sts_off[i], As + (size_t)ldrows[i] * DIM + g_c16 * 8);    \
            cp16(st + TILE_B + sts_off[i],                                      \
                 Bs + (size_t)ldrows[i] * DIM + g_c16 * 8);                     \
        }                                                                       \
        asm volatile("cp.async.commit_group;" ::: "memory");                    \
    }

    ISSUE_CHUNK(0, 0);

    for (int ch = 0; ch < NCHUNK; ch++) {
        int s = ch & 1;
        if (ch + 1 < NCHUNK) {
            ISSUE_CHUNK(ch + 1, s ^ 1);
            asm volatile("cp.async.wait_group 1;" ::: "memory");
        } else {
            asm volatile("cp.async.wait_group 0;" ::: "memory");
        }
        __syncthreads();

        uint32_t sa = sb + s * STAGE_B;
        uint32_t sB = sa + TILE_B;
#pragma unroll
        for (int ks = 0; ks < 4; ks++) {
            uint32_t a[4][4], bb[2][4];
#pragma unroll
            for (int mf = 0; mf < 4; mf++) {
                uint32_t addr = sa + SWZ((wm + mf * 16 + a_row) * 128 + ks * 32 + a_byte);
                ldm_x4(a[mf][0], a[mf][1], a[mf][2], a[mf][3], addr);
            }
#pragma unroll
            for (int nh = 0; nh < 2; nh++) {
                uint32_t addr = sB + SWZ((wn + nh * 16 + b_row) * 128 + ks * 32 + b_byte);
                ldm_x4(bb[nh][0], bb[nh][1], bb[nh][2], bb[nh][3], addr);
            }
#pragma unroll
            for (int mf = 0; mf < 4; mf++)
#pragma unroll
                for (int nf = 0; nf < 4; nf++)
                    mma_16816(acc[mf][nf], a[mf], bb[nf >> 1][(nf & 1) * 2],
                              bb[nf >> 1][(nf & 1) * 2 + 1]);
        }
        __syncthreads();
    }

    int g = lane >> 2, t4 = lane & 3;
#pragma unroll
    for (int mf = 0; mf < 4; mf++) {
#pragma unroll
        for (int nf = 0; nf < 4; nf++) {
            int row0 = bm + wm + mf * 16 + g;
            int col = bn + wn + nf * 8 + 2 * t4;
            float* p0 = g_sim + (size_t)row0 * N_TOT + col;
            float* p1 = p0 + 8 * N_TOT;
            *(float2*)p0 = make_float2(acc[mf][nf][0], acc[mf][nf][1]);
            *(float2*)p1 = make_float2(acc[mf][nf][2], acc[mf][nf][3]);
        }
    }
}

// ---------------------------------------------------------------------------
// Kernel 3: fused focal attention, thread-per-query + f32x2 quadratic forms,
// LDS.128 Gram rows, dual q-accumulator chains.
// Block = 288 threads = 4 pairs (same image, 4 captions), all parallel.
// ---------------------------------------------------------------------------
#define PPB 4

typedef unsigned long long ull;

__device__ __forceinline__ ull pk2(float x, float y) {
    ull r;
    asm("mov.b64 %0, {%1, %2};" : "=l"(r) : "f"(x), "f"(y));
    return r;
}
__device__ __forceinline__ void upk2(float& x, float& y, ull v) {
    asm("mov.b64 {%0, %1}, %2;" : "=f"(x), "=f"(y) : "l"(v));
}
__device__ __forceinline__ void fma2(ull& acc, ull a, ull b) {
    asm("fma.rn.f32x2 %0, %1, %2, %0;" : "+l"(acc) : "l"(a), "l"(b));
}
__device__ __forceinline__ ull add2(ull a, ull b) {
    ull r;
    asm("add.rn.f32x2 %0, %1, %2;" : "=l"(r) : "l"(a), "l"(b));
    return r;
}

__global__ void __launch_bounds__(288, 3) attn_kernel(float* __restrict__ out) {
    __shared__ float raw[PPB][N_REG][N_WORD + 1];
    __shared__ __align__(16) float G[N_REG][N_REG];
    __shared__ __align__(16) float Hs[PPB][N_WORD][N_WORD];
    __shared__ float nrmi[PPB][N_REG];
    __shared__ float nrmw[PPB][N_WORD];
    __shared__ float imn[N_REG];
    __shared__ float cpn[PPB][N_WORD];
    __shared__ float red[PPB][68];

    int i = blockIdx.y, c0 = blockIdx.x * PPB, t = threadIdx.x;

    for (int e = t; e < PPB * N_REG * N_WORD; e += 288) {
        int p = e / (N_REG * N_WORD), k = e % (N_REG * N_WORD);
        int w = k / N_REG, r = k % N_REG;
        raw[p][r][w] = g_sim[(size_t)((c0 + p) * N_WORD + w) * N_TOT + i * N_REG + r];
    }
    for (int e = t; e < N_REG * N_REG; e += 288)
        G[e / N_REG][e % N_REG] = g_G[i * N_REG * N_REG + e];
    for (int e = t; e < PPB * N_WORD * N_WORD; e += 288) {
        int p = e >> 10, k = e & 1023;
        Hs[p][k >> 5][k & 31] = g_H[(c0 + p) * N_WORD * N_WORD + k];
    }
    if (t < N_REG) imn[t] = g_imn[i * N_REG + t];
    if (t >= 128 && t < 128 + PPB * N_WORD) {
        int k = t - 128;
        cpn[k >> 5][k & 31] = g_cpn[(c0 + (k >> 5)) * N_WORD + (k & 31)];
    }
    __syncthreads();

    if (t < 128) {
        int p = t >> 5, w = t & 31;
        float s = 0.0f;
#pragma unroll
        for (int r = 0; r < N_REG; r++) {
            float x = raw[p][r][w];
            x = (x >= 0.0f) ? x : 0.1f * x;
            s += x * x;
        }
        nrmw[p][w] = 1.0f / (sqrtf(s) + EPSV);
    } else if (t < 272) {
        int k = t - 128, p = k / N_REG, r = k % N_REG;
        float s = 0.0f;
#pragma unroll
        for (int w = 0; w < N_WORD; w++) {
            float x = raw[p][r][w];
            x = (x >= 0.0f) ? x : 0.1f * x;
            s += x * x;
        }
        nrmi[p][r] = 1.0f / (sqrtf(s) + EPSV);
    }
    __syncthreads();

    if (t < 128) {
        // ===== t2i: one word per thread, S = 36 regions =====
        int p = t >> 5, w = t & 31;
        ull a2[18];
        float mx = -1e30f;
#pragma unroll
        for (int rp = 0; rp < 18; rp++) {
            float x0 = raw[p][2 * rp][w], x1 = raw[p][2 * rp + 1][w];
            x0 = (x0 >= 0.0f) ? x0 : 0.1f * x0;
            x1 = (x1 >= 0.0f) ? x1 : 0.1f * x1;
            x0 *= nrmi[p][2 * rp];
            x1 *= nrmi[p][2 * rp + 1];
            mx = fmaxf(mx, fmaxf(x0, x1));
            a2[rp] = pk2(x0, x1);
        }
        float s = 0.0f;
#pragma unroll
        for (int rp = 0; rp < 18; rp++) {
            float x0, x1; upk2(x0, x1, a2[rp]);
            x0 = __expf(LAMBDA_S * (x0 - mx));
            x1 = __expf(LAMBDA_S * (x1 - mx));
            s += x0 + x1;
            a2[rp] = pk2(x0, x1);
        }
        float inv = 1.0f / s;
        float sum1 = 0.0f;
#pragma unroll
        for (int rp = 0; rp < 18; rp++) {
            float x0, x1; upk2(x0, x1, a2[rp]);
            x0 *= inv; x1 *= inv;
            sum1 += x0 + x1;
            a2[rp] = pk2(x0, x1);
        }
        float st = 0.0f;
#pragma unroll
        for (int rp = 0; rp < 18; rp++) {
            float x0, x1; upk2(x0, x1, a2[rp]);
            x0 = (x0 * (float)N_REG - sum1 > 0.0f) ? x0 : 0.0f;
            x1 = (x1 * (float)N_REG - sum1 > 0.0f) ? x1 : 0.0f;
            st += x0 + x1;
            a2[rp] = pk2(x0, x1);
        }
        float invst = 1.0f / st;
        float num = 0.0f;
#pragma unroll
        for (int rp = 0; rp < 18; rp++) {
            float x0, x1; upk2(x0, x1, a2[rp]);
            x0 *= invst; x1 *= invst;
            num += x0 * raw[p][2 * rp][w] + x1 * raw[p][2 * rp + 1][w];
            a2[rp] = pk2(x0, x1);
        }
        float q0 = 0.0f, q1 = 0.0f;
#pragma unroll
        for (int rp = 0; rp < 18; rp++) {
            float ae, ao; upk2(ae, ao, a2[rp]);
            {
                const double2* Gr = (const double2*)&G[2 * rp][0];
                ull acc0 = 0, acc1 = 0;
#pragma unroll
                for (int j = 0; j < 9; j++) {
                    double2 g2 = Gr[j];
                    fma2(acc0, __double_as_longlong(g2.x), a2[2 * j]);
                    fma2(acc1, __double_as_longlong(g2.y), a2[2 * j + 1]);
                }
                float dx, dy; upk2(dx, dy, add2(acc0, acc1));
                q0 = fmaf(ae, dx + dy, q0);
            }
            {
                const double2* Gr = (const double2*)&G[2 * rp + 1][0];
                ull acc0 = 0, acc1 = 0;
#pragma unroll
                for (int j = 0; j < 9; j++) {
                    double2 g2 = Gr[j];
                    fma2(acc0, __double_as_longlong(g2.x), a2[2 * j]);
                    fma2(acc1, __double_as_longlong(g2.y), a2[2 * j + 1]);
                }
                float dx, dy; upk2(dx, dy, add2(acc0, acc1));
                q1 = fmaf(ao, dx + dy, q1);
            }
        }
        float q = q0 + q1;
        float nb = fmaxf(sqrtf(fmaxf(q, 0.0f)), EPSV);
        red[p][w] = num / (fmaxf(cpn[p][w], EPSV) * nb);
    } else if (t < 272) {
        // ===== i2t: one region per thread, S = 32 words =====
        int k = t - 128, p = k / N_REG, r = k % N_REG;
        ull a2[16];
        float mx = -1e30f;
#pragma unroll
        for (int wp = 0; wp < 16; wp++) {
            float x0 = raw[p][r][2 * wp], x1 = raw[p][r][2 * wp + 1];
            x0 = (x0 >= 0.0f) ? x0 : 0.1f * x0;
            x1 = (x1 >= 0.0f) ? x1 : 0.1f * x1;
            x0 *= nrmw[p][2 * wp];
            x1 *= nrmw[p][2 * wp + 1];
            mx = fmaxf(mx, fmaxf(x0, x1));
            a2[wp] = pk2(x0, x1);
        }
        float s = 0.0f;
#pragma unroll
        for (int wp = 0; wp < 16; wp++) {
            float x0, x1; upk2(x0, x1, a2[wp]);
            x0 = __expf(LAMBDA_S * (x0 - mx));
            x1 = __expf(LAMBDA_S * (x1 - mx));
            s += x0 + x1;
            a2[wp] = pk2(x0, x1);
        }
        float inv = 1.0f / s;
        float sum1 = 0.0f;
#pragma unroll
        for (int wp = 0; wp < 16; wp++) {
            float x0, x1; upk2(x0, x1, a2[wp]);
            x0 *= inv; x1 *= inv;
            sum1 += x0 + x1;
            a2[wp] = pk2(x0, x1);
        }
        float st = 0.0f;
#pragma unroll
        for (int wp = 0; wp < 16; wp++) {
            float x0, x1; upk2(x0, x1, a2[wp]);
            x0 = (x0 * (float)N_WORD - sum1 > 0.0f) ? x0 : 0.0f;
            x1 = (x1 * (float)N_WORD - sum1 > 0.0f) ? x1 : 0.0f;
            st += x0 + x1;
            a2[wp] = pk2(x0, x1);
        }
        float invst = 1.0f / st;
        float num = 0.0f;
#pragma unroll
        for (int wp = 0; wp < 16; wp++) {
            float x0, x1; upk2(x0, x1, a2[wp]);
            x0 *= invst; x1 *= invst;
            num += x0 * raw[p][r][2 * wp] + x1 * raw[p][r][2 * wp + 1];
            a2[wp] = pk2(x0, x1);
        }
        float q0 = 0.0f, q1 = 0.0f;
#pragma unroll
        for (int wp = 0; wp < 16; wp++) {
            float ae, ao; upk2(ae, ao, a2[wp]);
            {
                const double2* Hr = (const double2*)&Hs[p][2 * wp][0];
                ull acc0 = 0, acc1 = 0;
#pragma unroll
                for (int j = 0; j < 8; j++) {
                    double2 g2 = Hr[j];
                    fma2(acc0, __double_as_longlong(g2.x), a2[2 * j]);
                    fma2(acc1, __double_as_longlong(g2.y), a2[2 * j + 1]);
                }
                float dx, dy; upk2(dx, dy, add2(acc0, acc1));
                q0 = fmaf(ae, dx + dy, q0);
            }
            {
                const double2* Hr = (const double2*)&Hs[p][2 * wp + 1][0];
                ull acc0 = 0, acc1 = 0;
#pragma unroll
                for (int j = 0; j < 8; j++) {
                    double2 g2 = Hr[j];
                    fma2(acc0, __double_as_longlong(g2.x), a2[2 * j]);
                    fma2(acc1, __double_as_longlong(g2.y), a2[2 * j + 1]);
                }
                float dx, dy; upk2(dx, dy, add2(acc0, acc1));
                q1 = fmaf(ao, dx + dy, q1);
            }
        }
        float q = q0 + q1;
        float nb = fmaxf(sqrtf(fmaxf(q, 0.0f)), EPSV);
        red[p][32 + r] = num / (fmaxf(imn[r], EPSV) * nb);
    }
    __syncthreads();

    if (t < PPB) {
        float s1 = 0.0f;
#pragma unroll
        for (int w = 0; w < N_WORD; w++) s1 += red[t][w];
        float s2 = 0.0f;
#pragma unroll
        for (int r = 0; r < N_REG; r++) s2 += red[t][32 + r];
        out[i * N_CAP + (c0 + t)] = s1 / (float)N_WORD + s2 / (float)N_REG;
    }
}

// ---------------------------------------------------------------------------
extern "C" void kernel_launch(void* const* d_in, const int* in_sizes, int n_in,
                              void* d_out, int out_size) {
    const float* images = (const float*)d_in[0];
    const float* captions = (const float*)d_in[1];
    float* out = (float*)d_out;

    cudaFuncSetAttribute(gemm_mma, cudaFuncAttributeMaxDynamicSharedMemorySize,
                         GEMM_SMEM);

    split_kernel<<<2048, 256>>>(images, captions);
    gram_kernel<<<256, 256>>>(images, captions);
    gemm_mma<<<dim3(N_TOT / 128, M_TOT / 128), 256, GEMM_SMEM>>>();
    attn_kernel<<<dim3(N_CAP / PPB, N_IMG), 288>>>(out);
}